// round 5
// baseline (speedup 1.0000x reference)
#include <cuda_runtime.h>
#include <cuda_bf16.h>
#include <cstdint>

#define GD 160
#define GH 160
#define GW 160
#define CIN 32
#define COUT 64
#define NK 27
#define TILE_V 128
#define NMAX 400000

#if defined(__CUDA_ARCH_FEAT_SM103_ALL) || defined(__CUDA_ARCH_FEAT_SM100_ALL) || defined(__CUDA_ARCH_FEAT_SM101_ALL)
#define HAS_TCGEN05 1
#else
#define HAS_TCGEN05 0
#endif

// ---------------- device scratch (static globals: allowed) ----------------
__device__ int      g_grid[GD * GH * GW];        // 16.4 MB voxel -> row index
__device__ uint32_t g_packF[NMAX * CIN];         // 51.2 MB packed (bf16 hi | lo<<16)
__device__ uint32_t g_Bw[NK * 4096];             // 27 x 16KB pre-swizzled B tiles (pass1+pass2)

// ---------------- small PTX helpers ----------------
__device__ __forceinline__ uint32_t smem_u32(const void* p) {
    uint32_t a;
    asm("{ .reg .u64 t; cvta.to.shared.u64 t, %1; cvt.u32.u64 %0, t; }" : "=r"(a) : "l"(p));
    return a;
}

__host__ __device__ __forceinline__ uint32_t swz128(uint32_t off) {
    return off ^ ((off >> 3) & 0x70);
}

// SMEM descriptor: SW128, version=1, SBO=64 (1024B), LBO=1 (16B)
__device__ __forceinline__ uint64_t make_desc(uint32_t addr) {
    const uint64_t base =
        (uint64_t(2) << 61) | (uint64_t(1) << 46) | (uint64_t(64) << 32) | (uint64_t(1) << 16);
    return base | ((uint64_t)(addr >> 4) & 0x3FFF);
}

// idesc kind::f16: accum F32 (bit4), A=BF16 (bit7), B=BF16 (bit10), N=64 (8<<17), M=128 (8<<24)
#define MMA_IDESC 0x8100490u

#if HAS_TCGEN05
__device__ __forceinline__ void mma_f16_ss(uint32_t d_tmem, uint64_t a_desc,
                                           uint64_t b_desc, uint32_t en) {
    asm volatile(
        "{\n\t"
        ".reg .pred p;\n\t"
        "setp.ne.u32 p, %5, 0;\n\t"
        "tcgen05.mma.cta_group::1.kind::f16 [%0], %1, %2, %3, {%4, %4, %4, %4}, p;\n\t"
        "}"
        :: "r"(d_tmem), "l"(a_desc), "l"(b_desc), "r"(MMA_IDESC), "r"(0u), "r"(en)
        : "memory");
}
#endif

#define MBARRIER_WAIT_PARITY(mbar, parity) do {                                   \
    uint32_t _m = (mbar); uint32_t _p = (parity); uint32_t _done;                  \
    asm volatile(                                                                  \
        "{\n\t.reg .pred p;\n\t"                                                   \
        "mbarrier.try_wait.parity.acquire.cta.shared::cta.b64 p, [%1], %2;\n\t"    \
        "selp.b32 %0, 1, 0, p;\n\t}"                                               \
        : "=r"(_done) : "r"(_m), "r"(_p) : "memory");                              \
    if (!_done) {                                                                  \
        asm volatile(                                                              \
            "{\n\t.reg .pred P1;\n\t"                                              \
            "WL_%=:\n\t"                                                           \
            "mbarrier.try_wait.parity.acquire.cta.shared::cta.b64 P1, [%0], %1, 0x989680;\n\t" \
            "@P1 bra.uni WD_%=;\n\t"                                               \
            "bra.uni WL_%=;\n\t"                                                   \
            "WD_%=:\n\t}"                                                          \
            :: "r"(_m), "r"(_p) : "memory");                                       \
    }                                                                              \
} while (0)

// ---------------- prep kernels ----------------
__global__ void init_grid_kernel() {
    int i = blockIdx.x * blockDim.x + threadIdx.x;
    int4* p = reinterpret_cast<int4*>(g_grid);
    const int total = (GD * GH * GW) / 4;
    if (i < total) p[i] = make_int4(-1, -1, -1, -1);
}

__global__ void scatter_kernel(const int* __restrict__ coors, int n) {
    int i = blockIdx.x * blockDim.x + threadIdx.x;
    if (i < n) {
        int z = coors[4 * i + 1];
        int y = coors[4 * i + 2];
        int x = coors[4 * i + 3];
        g_grid[(z * GH + y) * GW + x] = i;
    }
}

__global__ void pack_features_kernel(const float* __restrict__ feat, int total) {
    int i = blockIdx.x * blockDim.x + threadIdx.x;
    if (i < total) {
        float x = feat[i];
        __nv_bfloat16 hi = __float2bfloat16(x);
        float r = x - __bfloat162float(hi);
        __nv_bfloat16 lo = __float2bfloat16(r);
        uint32_t w = (uint32_t)__bfloat16_as_ushort(hi) |
                     ((uint32_t)__bfloat16_as_ushort(lo) << 16);
        g_packF[i] = w;
    }
}

__global__ void pack_weights_kernel(const float* __restrict__ weight) {
    int i = blockIdx.x * blockDim.x + threadIdx.x;
    if (i >= NK * COUT * CIN) return;
    int k  = i / (COUT * CIN);
    int r  = i % (COUT * CIN);
    int nn = r / CIN;   // cout (B row)
    int c  = r % CIN;   // cin
    float w = weight[k * CIN * COUT + c * COUT + nn];
    __nv_bfloat16 hi = __float2bfloat16(w);
    float res = w - __bfloat162float(hi);
    __nv_bfloat16 lo = __float2bfloat16(res);
    uint32_t hb = __bfloat16_as_ushort(hi);
    uint32_t lb = __bfloat16_as_ushort(lo);
    uint32_t off = (uint32_t)(nn * 128 + c * 4);   // virtual cols 2c,2c+1
    uint32_t sw = swz128(off);
    g_Bw[k * 4096 + (sw >> 2)]        = hb | (hb << 16); // pass1: hi,hi
    g_Bw[k * 4096 + 2048 + (sw >> 2)] = lb;              // pass2: lo,0
}

// ---------------- main tensor-core kernel ----------------
// Depth-2 pipeline: gather/stage(k) overlaps MMA(k-1); wait is for MMA(k-2).
// Dynamic smem layout (1024-aligned): A0[16K] A1[16K] B0[16K] B1[16K].
__global__ __launch_bounds__(256) void conv_tc_kernel(
    const int*   __restrict__ coors,
    const float* __restrict__ bias,
    float*       __restrict__ out,
    int n)
{
#if HAS_TCGEN05
    extern __shared__ uint32_t dynsmem[];
    __shared__ int   sIdx[TILE_V];
    __shared__ int   sZ[TILE_V], sY[TILE_V], sX[TILE_V];
    __shared__ float sBias[COUT];
    __shared__ uint32_t sTmem;
    __shared__ __align__(8) uint64_t sMbar[2];

    const int tid = threadIdx.x;
    const int v0  = blockIdx.x * TILE_V;

    const uint32_t rawBase = smem_u32(dynsmem);
    const uint32_t aAddr   = (rawBase + 1023u) & ~1023u;      // 1024-aligned tile base
    uint32_t* sT = dynsmem + ((aAddr - rawBase) >> 2);        // word ptr at aAddr

    const uint32_t mbar0 = smem_u32(&sMbar[0]);
    const uint32_t mbar1 = smem_u32(&sMbar[1]);
    if (tid == 0) {
        asm volatile("mbarrier.init.shared.b64 [%0], 1;" :: "r"(mbar0) : "memory");
        asm volatile("mbarrier.init.shared.b64 [%0], 1;" :: "r"(mbar1) : "memory");
    }
    if (tid < COUT) sBias[tid] = bias[tid];
    if (tid < TILE_V) {
        int v = v0 + tid;
        if (v < n) {
            sZ[tid] = coors[4 * v + 1];
            sY[tid] = coors[4 * v + 2];
            sX[tid] = coors[4 * v + 3];
        } else {
            sZ[tid] = -1000; sY[tid] = -1000; sX[tid] = -1000;
        }
    }
    if (tid < 32) {
        uint32_t a = smem_u32(&sTmem);
        asm volatile("tcgen05.alloc.cta_group::1.sync.aligned.shared::cta.b32 [%0], %1;"
                     :: "r"(a), "r"(64u) : "memory");
        asm volatile("tcgen05.relinquish_alloc_permit.cta_group::1.sync.aligned;");
    }
    __syncthreads();

    const uint32_t tmem = sTmem;
    int ph0 = 0, ph1 = 0;   // per-stage consumed-commit counters

    for (int k = 0; k < NK; k++) {
        const int st = k & 1;
        const uint32_t aOffW = st ? 4096u : 0u;        // A stage word offset
        const uint32_t bOffW = st ? 12288u : 8192u;    // B stage word offset

        // Reuse guard: MMA(k-2) on this stage must be done before overwrite.
        if (k >= 2) {
            if (st == 0) { MBARRIER_WAIT_PARITY(mbar0, ph0 & 1); ph0++; }
            else         { MBARRIER_WAIT_PARITY(mbar1, ph1 & 1); ph1++; }
        }

        // Stage pre-swizzled B tiles (16KB): 1024 uint4, 4 per thread.
        {
            const uint4* src = reinterpret_cast<const uint4*>(g_Bw + k * 4096);
            uint4* dst = reinterpret_cast<uint4*>(sT + bOffW);
            dst[tid]       = src[tid];
            dst[tid + 256] = src[tid + 256];
            dst[tid + 512] = src[tid + 512];
            dst[tid + 768] = src[tid + 768];
        }
        // Neighbor lookup.
        if (tid < TILE_V) {
            const int dz = k / 9 - 1, dy = (k / 3) % 3 - 1, dx = k % 3 - 1;
            int z = sZ[tid] + dz, y = sY[tid] + dy, x = sX[tid] + dx;
            int idx = -1;
            if ((unsigned)z < GD && (unsigned)y < GH && (unsigned)x < GW)
                idx = g_grid[(z * GH + y) * GW + x];
            sIdx[tid] = idx;
        }
        __syncthreads();

        // Gather: warp = one voxel row -> coalesced 128B LDG, conflict-free swizzled STS.
        #pragma unroll
        for (int s = 0; s < 16; s++) {
            int slot = s * 256 + tid;
            int v = slot >> 5;
            int c = slot & 31;
            int idx = sIdx[v];
            uint32_t w = 0;
            if (idx >= 0) w = g_packF[idx * CIN + c];
            sT[aOffW + (swz128((uint32_t)(v * 128 + c * 4)) >> 2)] = w;
        }
        // Order generic-proxy writes vs async proxy in EVERY writer, then publish.
        asm volatile("fence.proxy.async.shared::cta;" ::: "memory");
        __syncthreads();

        if (tid == 0) {
            const uint64_t aD  = make_desc(aAddr + (st ? 16384u : 0u));
            const uint64_t b1D = make_desc(aAddr + (st ? 49152u : 32768u));
            const uint64_t b2D = b1D + 512;  // +8192 bytes in 16B units
            #pragma unroll
            for (int s = 0; s < 4; s++)   // pass1: (ahi+alo) * whi
                mma_f16_ss(tmem, aD + s * 2, b1D + s * 2, (k == 0 && s == 0) ? 0u : 1u);
            #pragma unroll
            for (int s = 0; s < 4; s++)   // pass2: ahi * wlo
                mma_f16_ss(tmem, aD + s * 2, b2D + s * 2, 1u);
            asm volatile(
                "tcgen05.commit.cta_group::1.mbarrier::arrive::one.shared::cluster.b64 [%0];"
                :: "r"(st == 0 ? mbar0 : mbar1) : "memory");
        }
    }

    // Drain the final commit on each stage (k=25 -> stage1, k=26 -> stage0).
    MBARRIER_WAIT_PARITY(mbar1, ph1 & 1);
    MBARRIER_WAIT_PARITY(mbar0, ph0 & 1);
    asm volatile("tcgen05.fence::after_thread_sync;" ::: "memory");

    // Epilogue: warpgroup 0 (threads 0..127) reads TMEM rows = voxels.
    if (tid < 128) {
        uint32_t r[64];
        asm volatile(
            "tcgen05.ld.sync.aligned.32x32b.x32.b32 "
            "{%0,%1,%2,%3,%4,%5,%6,%7,%8,%9,%10,%11,%12,%13,%14,%15,"
            "%16,%17,%18,%19,%20,%21,%22,%23,%24,%25,%26,%27,%28,%29,%30,%31}, [%32];"
            : "=r"(r[0]),"=r"(r[1]),"=r"(r[2]),"=r"(r[3]),"=r"(r[4]),"=r"(r[5]),"=r"(r[6]),"=r"(r[7]),
              "=r"(r[8]),"=r"(r[9]),"=r"(r[10]),"=r"(r[11]),"=r"(r[12]),"=r"(r[13]),"=r"(r[14]),"=r"(r[15]),
              "=r"(r[16]),"=r"(r[17]),"=r"(r[18]),"=r"(r[19]),"=r"(r[20]),"=r"(r[21]),"=r"(r[22]),"=r"(r[23]),
              "=r"(r[24]),"=r"(r[25]),"=r"(r[26]),"=r"(r[27]),"=r"(r[28]),"=r"(r[29]),"=r"(r[30]),"=r"(r[31])
            : "r"(tmem));
        asm volatile(
            "tcgen05.ld.sync.aligned.32x32b.x32.b32 "
            "{%0,%1,%2,%3,%4,%5,%6,%7,%8,%9,%10,%11,%12,%13,%14,%15,"
            "%16,%17,%18,%19,%20,%21,%22,%23,%24,%25,%26,%27,%28,%29,%30,%31}, [%32];"
            : "=r"(r[32]),"=r"(r[33]),"=r"(r[34]),"=r"(r[35]),"=r"(r[36]),"=r"(r[37]),"=r"(r[38]),"=r"(r[39]),
              "=r"(r[40]),"=r"(r[41]),"=r"(r[42]),"=r"(r[43]),"=r"(r[44]),"=r"(r[45]),"=r"(r[46]),"=r"(r[47]),
              "=r"(r[48]),"=r"(r[49]),"=r"(r[50]),"=r"(r[51]),"=r"(r[52]),"=r"(r[53]),"=r"(r[54]),"=r"(r[55]),
              "=r"(r[56]),"=r"(r[57]),"=r"(r[58]),"=r"(r[59]),"=r"(r[60]),"=r"(r[61]),"=r"(r[62]),"=r"(r[63])
            : "r"(tmem + 32));
        asm volatile("tcgen05.wait::ld.sync.aligned;" ::: "memory");

        int v = v0 + tid;
        if (v < n) {
            float4* op = reinterpret_cast<float4*>(out + (size_t)v * COUT);
            #pragma unroll
            for (int j = 0; j < 16; j++) {
                float4 o;
                o.x = __uint_as_float(r[4 * j + 0]) + sBias[4 * j + 0];
                o.y = __uint_as_float(r[4 * j + 1]) + sBias[4 * j + 1];
                o.z = __uint_as_float(r[4 * j + 2]) + sBias[4 * j + 2];
                o.w = __uint_as_float(r[4 * j + 3]) + sBias[4 * j + 3];
                op[j] = o;
            }
        }
    }

    __syncthreads();
    if (tid == 0) {
        asm volatile("mbarrier.inval.shared.b64 [%0];" :: "r"(mbar0) : "memory");
        asm volatile("mbarrier.inval.shared.b64 [%0];" :: "r"(mbar1) : "memory");
    }
    if (tid < 32) {
        asm volatile("tcgen05.dealloc.cta_group::1.sync.aligned.b32 %0, %1;" :: "r"(tmem), "r"(64u));
    }
#endif  // HAS_TCGEN05
}

extern "C" void kernel_launch(void* const* d_in, const int* in_sizes, int n_in,
                              void* d_out, int out_size) {
    const float* feat   = (const float*)d_in[0];
    const int*   coors  = (const int*)d_in[1];
    const float* weight = (const float*)d_in[2];
    const float* bias   = (const float*)d_in[3];
    float* out = (float*)d_out;
    const int n = in_sizes[0] / CIN;

    const int DYN_SMEM = 65536 + 1024;   // 4x16KB tiles + alignment slack
    cudaFuncSetAttribute(conv_tc_kernel, cudaFuncAttributeMaxDynamicSharedMemorySize, DYN_SMEM);

    init_grid_kernel<<<(GD * GH * GW / 4 + 255) / 256, 256>>>();
    scatter_kernel<<<(n + 255) / 256, 256>>>(coors, n);
    pack_features_kernel<<<(n * CIN + 255) / 256, 256>>>(feat, n * CIN);
    pack_weights_kernel<<<(NK * COUT * CIN + 255) / 256, 256>>>(weight);
    conv_tc_kernel<<<(n + TILE_V - 1) / TILE_V, 256, DYN_SMEM>>>(coors, bias, out, n);
}

// round 6
// speedup vs baseline: 1.3077x; 1.3077x over previous
#include <cuda_runtime.h>
#include <cuda_bf16.h>
#include <cstdint>

#define GD 160
#define GH 160
#define GW 160
#define CIN 32
#define COUT 64
#define NK 27
#define TILE_V 128
#define NMAX 400000

#if defined(__CUDA_ARCH_FEAT_SM103_ALL) || defined(__CUDA_ARCH_FEAT_SM100_ALL) || defined(__CUDA_ARCH_FEAT_SM101_ALL)
#define HAS_TCGEN05 1
#else
#define HAS_TCGEN05 0
#endif

// ---------------- device scratch ----------------
__device__ int      g_grid[GD * GH * GW];        // voxel -> row index
__device__ uint32_t g_packF[NMAX * CIN];         // packed (bf16 hi | lo<<16)
__device__ uint32_t g_Bw[NK * 4096];             // 27 x 16KB pre-swizzled B (pass1+pass2)

// ---------------- helpers ----------------
__device__ __forceinline__ uint32_t smem_u32(const void* p) {
    uint32_t a;
    asm("{ .reg .u64 t; cvta.to.shared.u64 t, %1; cvt.u32.u64 %0, t; }" : "=r"(a) : "l"(p));
    return a;
}

__host__ __device__ __forceinline__ uint32_t swz128(uint32_t off) {
    return off ^ ((off >> 3) & 0x70);
}

// SMEM descriptor: SW128, version=1, SBO=64 (1024B), LBO=1 (16B)
__device__ __forceinline__ uint64_t make_desc(uint32_t addr) {
    const uint64_t base =
        (uint64_t(2) << 61) | (uint64_t(1) << 46) | (uint64_t(64) << 32) | (uint64_t(1) << 16);
    return base | ((uint64_t)(addr >> 4) & 0x3FFF);
}

#define MMA_IDESC 0x8100490u   // F32 accum, A=BF16, B=BF16, N=64, M=128

#if HAS_TCGEN05
__device__ __forceinline__ void mma_f16_ss(uint32_t d_tmem, uint64_t a_desc,
                                           uint64_t b_desc, uint32_t en) {
    asm volatile(
        "{\n\t"
        ".reg .pred p;\n\t"
        "setp.ne.u32 p, %5, 0;\n\t"
        "tcgen05.mma.cta_group::1.kind::f16 [%0], %1, %2, %3, {%4, %4, %4, %4}, p;\n\t"
        "}"
        :: "r"(d_tmem), "l"(a_desc), "l"(b_desc), "r"(MMA_IDESC), "r"(0u), "r"(en)
        : "memory");
}
#endif

#define MBARRIER_WAIT_PARITY(mbar, parity) do {                                   \
    uint32_t _m = (mbar); uint32_t _p = (parity); uint32_t _done;                  \
    asm volatile(                                                                  \
        "{\n\t.reg .pred p;\n\t"                                                   \
        "mbarrier.try_wait.parity.acquire.cta.shared::cta.b64 p, [%1], %2;\n\t"    \
        "selp.b32 %0, 1, 0, p;\n\t}"                                               \
        : "=r"(_done) : "r"(_m), "r"(_p) : "memory");                              \
    if (!_done) {                                                                  \
        asm volatile(                                                              \
            "{\n\t.reg .pred P1;\n\t"                                              \
            "WL_%=:\n\t"                                                           \
            "mbarrier.try_wait.parity.acquire.cta.shared::cta.b64 P1, [%0], %1, 0x989680;\n\t" \
            "@P1 bra.uni WD_%=;\n\t"                                               \
            "bra.uni WL_%=;\n\t"                                                   \
            "WD_%=:\n\t}"                                                          \
            :: "r"(_m), "r"(_p) : "memory");                                       \
    }                                                                              \
} while (0)

// ---------------- prep kernels (2 launches so conv is launch #3) ----------------
__global__ void init_grid_kernel() {
    int i = blockIdx.x * blockDim.x + threadIdx.x;
    int4* p = reinterpret_cast<int4*>(g_grid);
    const int total = (GD * GH * GW) / 4;
    if (i < total) p[i] = make_int4(-1, -1, -1, -1);
}

// Fused: scatter + pack features + pack weights, dispatched by global thread id.
__global__ void prep_kernel(const int* __restrict__ coors,
                            const float* __restrict__ feat,
                            const float* __restrict__ weight,
                            int n) {
    int i = blockIdx.x * blockDim.x + threadIdx.x;
    const int nF = n * CIN;
    if (i < nF) {
        // pack features
        float x = feat[i];
        __nv_bfloat16 hi = __float2bfloat16(x);
        float r = x - __bfloat162float(hi);
        __nv_bfloat16 lo = __float2bfloat16(r);
        g_packF[i] = (uint32_t)__bfloat16_as_ushort(hi) |
                     ((uint32_t)__bfloat16_as_ushort(lo) << 16);
        return;
    }
    i -= nF;
    if (i < n) {
        // scatter
        int z = coors[4 * i + 1];
        int y = coors[4 * i + 2];
        int x = coors[4 * i + 3];
        g_grid[(z * GH + y) * GW + x] = i;
        return;
    }
    i -= n;
    if (i < NK * COUT * CIN) {
        // pack weights (pre-swizzled B tiles)
        int k  = i / (COUT * CIN);
        int rr = i % (COUT * CIN);
        int nn = rr / CIN;   // cout (B row)
        int c  = rr % CIN;   // cin
        float w = weight[k * CIN * COUT + c * COUT + nn];
        __nv_bfloat16 hi = __float2bfloat16(w);
        float res = w - __bfloat162float(hi);
        __nv_bfloat16 lo = __float2bfloat16(res);
        uint32_t hb = __bfloat16_as_ushort(hi);
        uint32_t lb = __bfloat16_as_ushort(lo);
        uint32_t sw = swz128((uint32_t)(nn * 128 + c * 4));
        g_Bw[k * 4096 + (sw >> 2)]        = hb | (hb << 16); // pass1: hi,hi
        g_Bw[k * 4096 + 2048 + (sw >> 2)] = lb;              // pass2: lo,0
    }
}

// ---------------- main tensor-core kernel ----------------
// Depth-2 pipeline; 128-bit vectorized gather (8 lanes per voxel row).
// Dynamic smem (1024-aligned): A0[16K] A1[16K] B0[16K] B1[16K].
__global__ __launch_bounds__(256) void conv_tc_kernel(
    const int*   __restrict__ coors,
    const float* __restrict__ bias,
    float*       __restrict__ out,
    int n)
{
#if HAS_TCGEN05
    extern __shared__ uint32_t dynsmem[];
    __shared__ int   sIdx[TILE_V];
    __shared__ int   sZ[TILE_V], sY[TILE_V], sX[TILE_V];
    __shared__ float sBias[COUT];
    __shared__ uint32_t sTmem;
    __shared__ __align__(8) uint64_t sMbar[2];

    const int tid = threadIdx.x;
    const int v0  = blockIdx.x * TILE_V;

    const uint32_t rawBase = smem_u32(dynsmem);
    const uint32_t aAddr   = (rawBase + 1023u) & ~1023u;
    uint32_t* sT = dynsmem + ((aAddr - rawBase) >> 2);

    const uint32_t mbar0 = smem_u32(&sMbar[0]);
    const uint32_t mbar1 = smem_u32(&sMbar[1]);
    if (tid == 0) {
        asm volatile("mbarrier.init.shared.b64 [%0], 1;" :: "r"(mbar0) : "memory");
        asm volatile("mbarrier.init.shared.b64 [%0], 1;" :: "r"(mbar1) : "memory");
    }
    if (tid < COUT) sBias[tid] = bias[tid];
    if (tid < TILE_V) {
        int v = v0 + tid;
        if (v < n) {
            sZ[tid] = coors[4 * v + 1];
            sY[tid] = coors[4 * v + 2];
            sX[tid] = coors[4 * v + 3];
        } else {
            sZ[tid] = -1000; sY[tid] = -1000; sX[tid] = -1000;
        }
    }
    if (tid < 32) {
        uint32_t a = smem_u32(&sTmem);
        asm volatile("tcgen05.alloc.cta_group::1.sync.aligned.shared::cta.b32 [%0], %1;"
                     :: "r"(a), "r"(64u) : "memory");
        asm volatile("tcgen05.relinquish_alloc_permit.cta_group::1.sync.aligned;");
    }
    __syncthreads();

    const uint32_t tmem = sTmem;
    int ph0 = 0, ph1 = 0;

    for (int k = 0; k < NK; k++) {
        const int st = k & 1;
        const uint32_t aOffW = st ? 4096u : 0u;
        const uint32_t bOffW = st ? 12288u : 8192u;

        if (k >= 2) {
            if (st == 0) { MBARRIER_WAIT_PARITY(mbar0, ph0 & 1); ph0++; }
            else         { MBARRIER_WAIT_PARITY(mbar1, ph1 & 1); ph1++; }
        }

        // Stage pre-swizzled B tiles (16KB): 4 uint4 per thread.
        {
            const uint4* src = reinterpret_cast<const uint4*>(g_Bw + k * 4096);
            uint4* dst = reinterpret_cast<uint4*>(sT + bOffW);
            dst[tid]       = src[tid];
            dst[tid + 256] = src[tid + 256];
            dst[tid + 512] = src[tid + 512];
            dst[tid + 768] = src[tid + 768];
        }
        // Neighbor lookup.
        if (tid < TILE_V) {
            const int dz = k / 9 - 1, dy = (k / 3) % 3 - 1, dx = k % 3 - 1;
            int z = sZ[tid] + dz, y = sY[tid] + dy, x = sX[tid] + dx;
            int idx = -1;
            if ((unsigned)z < GD && (unsigned)y < GH && (unsigned)x < GW)
                idx = g_grid[(z * GH + y) * GW + x];
            sIdx[tid] = idx;
        }
        __syncthreads();

        // Vectorized gather: 1024 uint4 slots (128 rows x 8 quads), 4 per thread.
        // Lane group of 8 covers one 128B row: LDG.128 coalesced, STS.128 at
        // swizzled quad (q ^ (v&7)) -- conflict-free.
        uint4* aDst = reinterpret_cast<uint4*>(sT + aOffW);
        #pragma unroll
        for (int s = 0; s < 4; s++) {
            int slot = s * 256 + tid;
            int v = slot >> 3;
            int q = slot & 7;
            int idx = sIdx[v];
            uint4 val = make_uint4(0u, 0u, 0u, 0u);
            if (idx >= 0)
                val = reinterpret_cast<const uint4*>(g_packF)[idx * 8 + q];
            aDst[v * 8 + (q ^ (v & 7))] = val;
        }
        asm volatile("fence.proxy.async.shared::cta;" ::: "memory");
        __syncthreads();

        if (tid == 0) {
            const uint64_t aD  = make_desc(aAddr + (st ? 16384u : 0u));
            const uint64_t b1D = make_desc(aAddr + (st ? 49152u : 32768u));
            const uint64_t b2D = b1D + 512;
            #pragma unroll
            for (int s = 0; s < 4; s++)   // pass1: (ahi+alo) * whi
                mma_f16_ss(tmem, aD + s * 2, b1D + s * 2, (k == 0 && s == 0) ? 0u : 1u);
            #pragma unroll
            for (int s = 0; s < 4; s++)   // pass2: ahi * wlo
                mma_f16_ss(tmem, aD + s * 2, b2D + s * 2, 1u);
            asm volatile(
                "tcgen05.commit.cta_group::1.mbarrier::arrive::one.shared::cluster.b64 [%0];"
                :: "r"(st == 0 ? mbar0 : mbar1) : "memory");
        }
    }

    MBARRIER_WAIT_PARITY(mbar1, ph1 & 1);
    MBARRIER_WAIT_PARITY(mbar0, ph0 & 1);
    asm volatile("tcgen05.fence::after_thread_sync;" ::: "memory");

    // Epilogue: warpgroup 0 reads TMEM rows = voxels.
    if (tid < 128) {
        uint32_t r[64];
        asm volatile(
            "tcgen05.ld.sync.aligned.32x32b.x32.b32 "
            "{%0,%1,%2,%3,%4,%5,%6,%7,%8,%9,%10,%11,%12,%13,%14,%15,"
            "%16,%17,%18,%19,%20,%21,%22,%23,%24,%25,%26,%27,%28,%29,%30,%31}, [%32];"
            : "=r"(r[0]),"=r"(r[1]),"=r"(r[2]),"=r"(r[3]),"=r"(r[4]),"=r"(r[5]),"=r"(r[6]),"=r"(r[7]),
              "=r"(r[8]),"=r"(r[9]),"=r"(r[10]),"=r"(r[11]),"=r"(r[12]),"=r"(r[13]),"=r"(r[14]),"=r"(r[15]),
              "=r"(r[16]),"=r"(r[17]),"=r"(r[18]),"=r"(r[19]),"=r"(r[20]),"=r"(r[21]),"=r"(r[22]),"=r"(r[23]),
              "=r"(r[24]),"=r"(r[25]),"=r"(r[26]),"=r"(r[27]),"=r"(r[28]),"=r"(r[29]),"=r"(r[30]),"=r"(r[31])
            : "r"(tmem));
        asm volatile(
            "tcgen05.ld.sync.aligned.32x32b.x32.b32 "
            "{%0,%1,%2,%3,%4,%5,%6,%7,%8,%9,%10,%11,%12,%13,%14,%15,"
            "%16,%17,%18,%19,%20,%21,%22,%23,%24,%25,%26,%27,%28,%29,%30,%31}, [%32];"
            : "=r"(r[32]),"=r"(r[33]),"=r"(r[34]),"=r"(r[35]),"=r"(r[36]),"=r"(r[37]),"=r"(r[38]),"=r"(r[39]),
              "=r"(r[40]),"=r"(r[41]),"=r"(r[42]),"=r"(r[43]),"=r"(r[44]),"=r"(r[45]),"=r"(r[46]),"=r"(r[47]),
              "=r"(r[48]),"=r"(r[49]),"=r"(r[50]),"=r"(r[51]),"=r"(r[52]),"=r"(r[53]),"=r"(r[54]),"=r"(r[55]),
              "=r"(r[56]),"=r"(r[57]),"=r"(r[58]),"=r"(r[59]),"=r"(r[60]),"=r"(r[61]),"=r"(r[62]),"=r"(r[63])
            : "r"(tmem + 32));
        asm volatile("tcgen05.wait::ld.sync.aligned;" ::: "memory");

        int v = v0 + tid;
        if (v < n) {
            float4* op = reinterpret_cast<float4*>(out + (size_t)v * COUT);
            #pragma unroll
            for (int j = 0; j < 16; j++) {
                float4 o;
                o.x = __uint_as_float(r[4 * j + 0]) + sBias[4 * j + 0];
                o.y = __uint_as_float(r[4 * j + 1]) + sBias[4 * j + 1];
                o.z = __uint_as_float(r[4 * j + 2]) + sBias[4 * j + 2];
                o.w = __uint_as_float(r[4 * j + 3]) + sBias[4 * j + 3];
                op[j] = o;
            }
        }
    }

    __syncthreads();
    if (tid == 0) {
        asm volatile("mbarrier.inval.shared.b64 [%0];" :: "r"(mbar0) : "memory");
        asm volatile("mbarrier.inval.shared.b64 [%0];" :: "r"(mbar1) : "memory");
    }
    if (tid < 32) {
        asm volatile("tcgen05.dealloc.cta_group::1.sync.aligned.b32 %0, %1;" :: "r"(tmem), "r"(64u));
    }
#endif  // HAS_TCGEN05
}

extern "C" void kernel_launch(void* const* d_in, const int* in_sizes, int n_in,
                              void* d_out, int out_size) {
    const float* feat   = (const float*)d_in[0];
    const int*   coors  = (const int*)d_in[1];
    const float* weight = (const float*)d_in[2];
    const float* bias   = (const float*)d_in[3];
    float* out = (float*)d_out;
    const int n = in_sizes[0] / CIN;

    const int DYN_SMEM = 65536 + 1024;
    cudaFuncSetAttribute(conv_tc_kernel, cudaFuncAttributeMaxDynamicSharedMemorySize, DYN_SMEM);

    init_grid_kernel<<<(GD * GH * GW / 4 + 255) / 256, 256>>>();
    const int prep_threads = n * CIN + n + NK * COUT * CIN;
    prep_kernel<<<(prep_threads + 255) / 256, 256>>>(coors, feat, weight, n);
    conv_tc_kernel<<<(n + TILE_V - 1) / TILE_V, 256, DYN_SMEM>>>(coors, bias, out, n);
}

// round 7
// speedup vs baseline: 1.5480x; 1.1837x over previous
#include <cuda_runtime.h>
#include <cuda_bf16.h>
#include <cstdint>

#define GD 160
#define GH 160
#define GW 160
#define CIN 32
#define COUT 64
#define NK 27
#define TILE_V 128
#define NMAX 400000

#if defined(__CUDA_ARCH_FEAT_SM103_ALL) || defined(__CUDA_ARCH_FEAT_SM100_ALL) || defined(__CUDA_ARCH_FEAT_SM101_ALL)
#define HAS_TCGEN05 1
#else
#define HAS_TCGEN05 0
#endif

// ---------------- device scratch ----------------
__device__ int      g_grid[GD * GH * GW];        // voxel -> row index
__device__ uint32_t g_packF[NMAX * CIN];         // packed (bf16 hi | lo<<16)
__device__ uint32_t g_Bw[NK * 4096];             // 27 x 16KB pre-swizzled B (pass1+pass2)

// ---------------- helpers ----------------
__device__ __forceinline__ uint32_t smem_u32(const void* p) {
    uint32_t a;
    asm("{ .reg .u64 t; cvta.to.shared.u64 t, %1; cvt.u32.u64 %0, t; }" : "=r"(a) : "l"(p));
    return a;
}

__host__ __device__ __forceinline__ uint32_t swz128(uint32_t off) {
    return off ^ ((off >> 3) & 0x70);
}

// SMEM descriptor: SW128, version=1, SBO=64 (1024B), LBO=1 (16B)
__device__ __forceinline__ uint64_t make_desc(uint32_t addr) {
    const uint64_t base =
        (uint64_t(2) << 61) | (uint64_t(1) << 46) | (uint64_t(64) << 32) | (uint64_t(1) << 16);
    return base | ((uint64_t)(addr >> 4) & 0x3FFF);
}

#define MMA_IDESC 0x8100490u   // F32 accum, A=BF16, B=BF16, N=64, M=128

#if HAS_TCGEN05
__device__ __forceinline__ void mma_f16_ss(uint32_t d_tmem, uint64_t a_desc,
                                           uint64_t b_desc, uint32_t en) {
    asm volatile(
        "{\n\t"
        ".reg .pred p;\n\t"
        "setp.ne.u32 p, %5, 0;\n\t"
        "tcgen05.mma.cta_group::1.kind::f16 [%0], %1, %2, %3, {%4, %4, %4, %4}, p;\n\t"
        "}"
        :: "r"(d_tmem), "l"(a_desc), "l"(b_desc), "r"(MMA_IDESC), "r"(0u), "r"(en)
        : "memory");
}
#endif

#define MBARRIER_WAIT_PARITY(mbar, parity) do {                                   \
    uint32_t _m = (mbar); uint32_t _p = (parity); uint32_t _done;                  \
    asm volatile(                                                                  \
        "{\n\t.reg .pred p;\n\t"                                                   \
        "mbarrier.try_wait.parity.acquire.cta.shared::cta.b64 p, [%1], %2;\n\t"    \
        "selp.b32 %0, 1, 0, p;\n\t}"                                               \
        : "=r"(_done) : "r"(_m), "r"(_p) : "memory");                              \
    if (!_done) {                                                                  \
        asm volatile(                                                              \
            "{\n\t.reg .pred P1;\n\t"                                              \
            "WL_%=:\n\t"                                                           \
            "mbarrier.try_wait.parity.acquire.cta.shared::cta.b64 P1, [%0], %1, 0x989680;\n\t" \
            "@P1 bra.uni WD_%=;\n\t"                                               \
            "bra.uni WL_%=;\n\t"                                                   \
            "WD_%=:\n\t}"                                                          \
            :: "r"(_m), "r"(_p) : "memory");                                       \
    }                                                                              \
} while (0)

// ---------------- prep kernels ----------------
__global__ void init_grid_kernel() {
    int i = blockIdx.x * blockDim.x + threadIdx.x;
    int4* p = reinterpret_cast<int4*>(g_grid);
    const int total = (GD * GH * GW) / 4;
    if (i < total) p[i] = make_int4(-1, -1, -1, -1);
}

// Fused: pack features + scatter + pack weights, dispatched by global thread id.
__global__ void prep_kernel(const int* __restrict__ coors,
                            const float* __restrict__ feat,
                            const float* __restrict__ weight,
                            int n) {
    int i = blockIdx.x * blockDim.x + threadIdx.x;
    const int nF = n * CIN;
    if (i < nF) {
        float x = feat[i];
        __nv_bfloat16 hi = __float2bfloat16(x);
        float r = x - __bfloat162float(hi);
        __nv_bfloat16 lo = __float2bfloat16(r);
        g_packF[i] = (uint32_t)__bfloat16_as_ushort(hi) |
                     ((uint32_t)__bfloat16_as_ushort(lo) << 16);
        return;
    }
    i -= nF;
    if (i < n) {
        int z = coors[4 * i + 1];
        int y = coors[4 * i + 2];
        int x = coors[4 * i + 3];
        g_grid[(z * GH + y) * GW + x] = i;
        return;
    }
    i -= n;
    if (i < NK * COUT * CIN) {
        int k  = i / (COUT * CIN);
        int rr = i % (COUT * CIN);
        int nn = rr / CIN;   // cout (B row)
        int c  = rr % CIN;   // cin
        float w = weight[k * CIN * COUT + c * COUT + nn];
        __nv_bfloat16 hi = __float2bfloat16(w);
        float res = w - __bfloat162float(hi);
        __nv_bfloat16 lo = __float2bfloat16(res);
        uint32_t hb = __bfloat16_as_ushort(hi);
        uint32_t lb = __bfloat16_as_ushort(lo);
        uint32_t sw = swz128((uint32_t)(nn * 128 + c * 4));
        g_Bw[k * 4096 + (sw >> 2)]        = hb | (hb << 16); // pass1: hi,hi
        g_Bw[k * 4096 + 2048 + (sw >> 2)] = lb;              // pass2: lo,0
    }
}

// ---------------- main tensor-core kernel ----------------
// Depth-2 pipeline; B staged via TMA bulk copy; neighbor lookup prefetched
// one k ahead; ONE __syncthreads per iteration.
// Dynamic smem (1024-aligned): A0[16K] A1[16K] B0[16K] B1[16K].
__global__ __launch_bounds__(256) void conv_tc_kernel(
    const int*   __restrict__ coors,
    const float* __restrict__ bias,
    float*       __restrict__ out,
    int n)
{
#if HAS_TCGEN05
    extern __shared__ uint32_t dynsmem[];
    __shared__ int   sIdx[2][TILE_V];      // double-buffered neighbor indices
    __shared__ int   sZ[TILE_V], sY[TILE_V], sX[TILE_V];
    __shared__ float sBias[COUT];
    __shared__ uint32_t sTmem;
    __shared__ __align__(8) uint64_t sMbarMMA[2];
    __shared__ __align__(8) uint64_t sMbarTMA[2];

    const int tid = threadIdx.x;
    const int v0  = blockIdx.x * TILE_V;

    const uint32_t rawBase = smem_u32(dynsmem);
    const uint32_t aAddr   = (rawBase + 1023u) & ~1023u;
    uint32_t* sT = dynsmem + ((aAddr - rawBase) >> 2);

    const uint32_t mbarM0 = smem_u32(&sMbarMMA[0]);
    const uint32_t mbarM1 = smem_u32(&sMbarMMA[1]);
    const uint32_t mbarT0 = smem_u32(&sMbarTMA[0]);
    const uint32_t mbarT1 = smem_u32(&sMbarTMA[1]);
    if (tid == 0) {
        asm volatile("mbarrier.init.shared.b64 [%0], 1;" :: "r"(mbarM0) : "memory");
        asm volatile("mbarrier.init.shared.b64 [%0], 1;" :: "r"(mbarM1) : "memory");
        asm volatile("mbarrier.init.shared.b64 [%0], 1;" :: "r"(mbarT0) : "memory");
        asm volatile("mbarrier.init.shared.b64 [%0], 1;" :: "r"(mbarT1) : "memory");
    }
    if (tid < COUT) sBias[tid] = bias[tid];
    if (tid < TILE_V) {
        int v = v0 + tid;
        int z, y, x;
        if (v < n) {
            z = coors[4 * v + 1];
            y = coors[4 * v + 2];
            x = coors[4 * v + 3];
        } else {
            z = -1000; y = -1000; x = -1000;
        }
        sZ[tid] = z; sY[tid] = y; sX[tid] = x;
        // Prologue lookup for k=0 (dz=dy=dx=-1).
        int nz = z - 1, ny = y - 1, nx = x - 1;
        int idx = -1;
        if ((unsigned)nz < GD && (unsigned)ny < GH && (unsigned)nx < GW)
            idx = g_grid[(nz * GH + ny) * GW + nx];
        sIdx[0][tid] = idx;
    }
    if (tid < 32) {
        uint32_t a = smem_u32(&sTmem);
        asm volatile("tcgen05.alloc.cta_group::1.sync.aligned.shared::cta.b32 [%0], %1;"
                     :: "r"(a), "r"(64u) : "memory");
        asm volatile("tcgen05.relinquish_alloc_permit.cta_group::1.sync.aligned;");
    }
    __syncthreads();

    const uint32_t tmem = sTmem;
    int phM0 = 0, phM1 = 0;   // MMA-done consumed counters (all threads)
    int phT0 = 0, phT1 = 0;   // TMA-done consumed counters (tid 0 only)

    for (int k = 0; k < NK; k++) {
        const int st = k & 1;
        const uint32_t aOffW = st ? 4096u : 0u;

        // Reuse guard: MMA(k-2) on this stage must be done before A/B overwrite.
        if (k >= 2) {
            if (st == 0) { MBARRIER_WAIT_PARITY(mbarM0, phM0 & 1); phM0++; }
            else         { MBARRIER_WAIT_PARITY(mbarM1, phM1 & 1); phM1++; }
        }

        // Kick B(k) via TMA bulk copy into stage st (async; LSU-free).
        if (tid == 0) {
            const uint32_t mbT = st == 0 ? mbarT0 : mbarT1;
            const uint32_t bSm = aAddr + 32768u + (st ? 16384u : 0u);
            asm volatile(
                "mbarrier.arrive.expect_tx.shared.b64 _, [%0], %1;"
                :: "r"(mbT), "r"(16384u) : "memory");
            asm volatile(
                "cp.async.bulk.shared::cta.global.mbarrier::complete_tx::bytes "
                "[%0], [%1], %2, [%3];"
                :: "r"(bSm), "l"((const void*)(g_Bw + k * 4096)), "r"(16384u), "r"(mbT)
                : "memory");
        }

        // Vectorized A gather using prefetched sIdx[st]: 8 lanes per 128B row.
        uint4* aDst = reinterpret_cast<uint4*>(sT + aOffW);
        const int* idxBuf = sIdx[st];
        #pragma unroll
        for (int s = 0; s < 4; s++) {
            int slot = s * 256 + tid;
            int v = slot >> 3;
            int q = slot & 7;
            int idx = idxBuf[v];
            uint4 val = make_uint4(0u, 0u, 0u, 0u);
            if (idx >= 0)
                val = reinterpret_cast<const uint4*>(g_packF)[idx * 8 + q];
            aDst[v * 8 + (q ^ (v & 7))] = val;
        }

        // Prefetch neighbor lookup for k+1 into the other sIdx buffer.
        if (k + 1 < NK && tid < TILE_V) {
            const int kn = k + 1;
            const int dz = kn / 9 - 1, dy = (kn / 3) % 3 - 1, dx = kn % 3 - 1;
            int z = sZ[tid] + dz, y = sY[tid] + dy, x = sX[tid] + dx;
            int idx = -1;
            if ((unsigned)z < GD && (unsigned)y < GH && (unsigned)x < GW)
                idx = g_grid[(z * GH + y) * GW + x];
            sIdx[st ^ 1][tid] = idx;
        }

        // Publish A writes to the async proxy, then to all threads.
        asm volatile("fence.proxy.async.shared::cta;" ::: "memory");
        __syncthreads();

        if (tid == 0) {
            // Wait for B(k) TMA completion (only the MMA issuer needs it).
            if (st == 0) { MBARRIER_WAIT_PARITY(mbarT0, phT0 & 1); phT0++; }
            else         { MBARRIER_WAIT_PARITY(mbarT1, phT1 & 1); phT1++; }

            const uint64_t aD  = make_desc(aAddr + (st ? 16384u : 0u));
            const uint64_t b1D = make_desc(aAddr + 32768u + (st ? 16384u : 0u));
            const uint64_t b2D = b1D + 512;  // +8192 B in 16B units
            #pragma unroll
            for (int s = 0; s < 4; s++)   // pass1: (ahi+alo) * whi
                mma_f16_ss(tmem, aD + s * 2, b1D + s * 2, (k == 0 && s == 0) ? 0u : 1u);
            #pragma unroll
            for (int s = 0; s < 4; s++)   // pass2: ahi * wlo
                mma_f16_ss(tmem, aD + s * 2, b2D + s * 2, 1u);
            asm volatile(
                "tcgen05.commit.cta_group::1.mbarrier::arrive::one.shared::cluster.b64 [%0];"
                :: "r"(st == 0 ? mbarM0 : mbarM1) : "memory");
        }
    }

    // Drain final commits (k=25 -> stage1, k=26 -> stage0).
    MBARRIER_WAIT_PARITY(mbarM1, phM1 & 1);
    MBARRIER_WAIT_PARITY(mbarM0, phM0 & 1);
    asm volatile("tcgen05.fence::after_thread_sync;" ::: "memory");

    // Epilogue: warpgroup 0 reads TMEM rows = voxels.
    if (tid < 128) {
        uint32_t r[64];
        asm volatile(
            "tcgen05.ld.sync.aligned.32x32b.x32.b32 "
            "{%0,%1,%2,%3,%4,%5,%6,%7,%8,%9,%10,%11,%12,%13,%14,%15,"
            "%16,%17,%18,%19,%20,%21,%22,%23,%24,%25,%26,%27,%28,%29,%30,%31}, [%32];"
            : "=r"(r[0]),"=r"(r[1]),"=r"(r[2]),"=r"(r[3]),"=r"(r[4]),"=r"(r[5]),"=r"(r[6]),"=r"(r[7]),
              "=r"(r[8]),"=r"(r[9]),"=r"(r[10]),"=r"(r[11]),"=r"(r[12]),"=r"(r[13]),"=r"(r[14]),"=r"(r[15]),
              "=r"(r[16]),"=r"(r[17]),"=r"(r[18]),"=r"(r[19]),"=r"(r[20]),"=r"(r[21]),"=r"(r[22]),"=r"(r[23]),
              "=r"(r[24]),"=r"(r[25]),"=r"(r[26]),"=r"(r[27]),"=r"(r[28]),"=r"(r[29]),"=r"(r[30]),"=r"(r[31])
            : "r"(tmem));
        asm volatile(
            "tcgen05.ld.sync.aligned.32x32b.x32.b32 "
            "{%0,%1,%2,%3,%4,%5,%6,%7,%8,%9,%10,%11,%12,%13,%14,%15,"
            "%16,%17,%18,%19,%20,%21,%22,%23,%24,%25,%26,%27,%28,%29,%30,%31}, [%32];"
            : "=r"(r[32]),"=r"(r[33]),"=r"(r[34]),"=r"(r[35]),"=r"(r[36]),"=r"(r[37]),"=r"(r[38]),"=r"(r[39]),
              "=r"(r[40]),"=r"(r[41]),"=r"(r[42]),"=r"(r[43]),"=r"(r[44]),"=r"(r[45]),"=r"(r[46]),"=r"(r[47]),
              "=r"(r[48]),"=r"(r[49]),"=r"(r[50]),"=r"(r[51]),"=r"(r[52]),"=r"(r[53]),"=r"(r[54]),"=r"(r[55]),
              "=r"(r[56]),"=r"(r[57]),"=r"(r[58]),"=r"(r[59]),"=r"(r[60]),"=r"(r[61]),"=r"(r[62]),"=r"(r[63])
            : "r"(tmem + 32));
        asm volatile("tcgen05.wait::ld.sync.aligned;" ::: "memory");

        int v = v0 + tid;
        if (v < n) {
            float4* op = reinterpret_cast<float4*>(out + (size_t)v * COUT);
            #pragma unroll
            for (int j = 0; j < 16; j++) {
                float4 o;
                o.x = __uint_as_float(r[4 * j + 0]) + sBias[4 * j + 0];
                o.y = __uint_as_float(r[4 * j + 1]) + sBias[4 * j + 1];
                o.z = __uint_as_float(r[4 * j + 2]) + sBias[4 * j + 2];
                o.w = __uint_as_float(r[4 * j + 3]) + sBias[4 * j + 3];
                op[j] = o;
            }
        }
    }

    __syncthreads();
    if (tid == 0) {
        asm volatile("mbarrier.inval.shared.b64 [%0];" :: "r"(mbarM0) : "memory");
        asm volatile("mbarrier.inval.shared.b64 [%0];" :: "r"(mbarM1) : "memory");
        asm volatile("mbarrier.inval.shared.b64 [%0];" :: "r"(mbarT0) : "memory");
        asm volatile("mbarrier.inval.shared.b64 [%0];" :: "r"(mbarT1) : "memory");
    }
    if (tid < 32) {
        asm volatile("tcgen05.dealloc.cta_group::1.sync.aligned.b32 %0, %1;" :: "r"(tmem), "r"(64u));
    }
#endif  // HAS_TCGEN05
}

extern "C" void kernel_launch(void* const* d_in, const int* in_sizes, int n_in,
                              void* d_out, int out_size) {
    const float* feat   = (const float*)d_in[0];
    const int*   coors  = (const int*)d_in[1];
    const float* weight = (const float*)d_in[2];
    const float* bias   = (const float*)d_in[3];
    float* out = (float*)d_out;
    const int n = in_sizes[0] / CIN;

    const int DYN_SMEM = 65536 + 1024;
    cudaFuncSetAttribute(conv_tc_kernel, cudaFuncAttributeMaxDynamicSharedMemorySize, DYN_SMEM);

    init_grid_kernel<<<(GD * GH * GW / 4 + 255) / 256, 256>>>();
    const int prep_threads = n * CIN + n + NK * COUT * CIN;
    prep_kernel<<<(prep_threads + 255) / 256, 256>>>(coors, feat, weight, n);
    conv_tc_kernel<<<(n + TILE_V - 1) / TILE_V, 256, DYN_SMEM>>>(coors, bias, out, n);
}